// round 14
// baseline (speedup 1.0000x reference)
#include <cuda_runtime.h>
#include <stdint.h>

#define DD 128
#define NMAX 50000
#define EMAX 800000
#define NB ((size_t)NMAX * DD)

// scratch (static device memory — no allocs)
__device__ __align__(16) float g_buf[6 * NB];
__device__ __align__(16) float g_w[4 * DD * DD];   // tf32-rounded W, Wt, W1, W2
__device__ __align__(16) float g_ww1[DD * DD];     // rnd(W_r @ W1_r)
__device__ float g_bb1[DD];                        // b @ W1_r + b1
__device__ float g_stats[512];   // [set][{sum,sumsq}][128]
__device__ float g_bnp[512];     // [set][{mu, gamma*rstd}][128]
__device__ float g_loss;
// CSR build
__device__ int   g_cnt[NMAX + 1];
__device__ int   g_cursor[NMAX];
__device__ int   g_blksum[64];
__device__ int   g_blkoff[64];
__device__ __align__(8) int2 g_epk[EMAX];          // packed {col, val-bits}

__device__ __forceinline__ float rnd_tf32(float f) {
    uint32_t u;
    asm("cvt.rna.tf32.f32 %0, %1;" : "=r"(u) : "f"(f));
    return __uint_as_float(u);
}

__device__ __forceinline__ uint32_t rndu(uint32_t u) {
    uint32_t o;
    asm("cvt.rna.tf32.f32 %0, %1;" : "=r"(o) : "f"(__uint_as_float(u)));
    return o;
}

__device__ __forceinline__ uint32_t bnfrag(uint32_t u, float g, float bp, float alpha) {
    float v = __uint_as_float(u);
    v = fmaf(v, g, bp);
    v = fmaxf(v, 0.f) + alpha * fminf(v, 0.f);
    uint32_t o;
    asm("cvt.rna.tf32.f32 %0, %1;" : "=r"(o) : "f"(v));
    return o;
}

__device__ __forceinline__ void mma_tf32(float& d0, float& d1, float& d2, float& d3,
                                         uint32_t a0, uint32_t a1, uint32_t a2, uint32_t a3,
                                         uint32_t b0, uint32_t b1) {
    asm volatile(
        "mma.sync.aligned.m16n8k8.row.col.f32.tf32.tf32.f32 "
        "{%0,%1,%2,%3}, {%4,%5,%6,%7}, {%8,%9}, {%0,%1,%2,%3};"
        : "+f"(d0), "+f"(d1), "+f"(d2), "+f"(d3)
        : "r"(a0), "r"(a1), "r"(a2), "r"(a3), "r"(b0), "r"(b1));
}

__device__ __forceinline__ uint32_t smem_u32(const void* p) {
    uint32_t a;
    asm("{ .reg .u64 t; cvta.to.shared.u64 t, %1; cvt.u32.u64 %0, t; }" : "=r"(a) : "l"(p));
    return a;
}

__device__ __forceinline__ void cp16(uint32_t dst, const void* src, bool pred) {
    int sz = pred ? 16 : 0;
    asm volatile("cp.async.cg.shared.global [%0], [%1], 16, %2;"
                 :: "r"(dst), "l"(src), "r"(sz) : "memory");
}
#define CP_COMMIT() asm volatile("cp.async.commit_group;" ::: "memory")

// ---------------------------------------------------------------------------
// init: zero hist/stats/loss; round weight matrices into g_w
// ---------------------------------------------------------------------------
__global__ void init_kernel(const float* __restrict__ W, const float* __restrict__ Wt,
                            const float* __restrict__ W1, const float* __restrict__ W2,
                            int n) {
    int i = blockIdx.x * blockDim.x + threadIdx.x;
    if (i < 512) g_stats[i] = 0.f;
    if (i == 0) g_loss = 0.f;
    if (i <= n) g_cnt[i] = 0;
    if (i < DD * DD) {
        g_w[i]               = rnd_tf32(W[i]);
        g_w[DD * DD + i]     = rnd_tf32(Wt[i]);
        g_w[2 * DD * DD + i] = rnd_tf32(W1[i]);
        g_w[3 * DD * DD + i] = rnd_tf32(W2[i]);
    }
}

// ---------------------------------------------------------------------------
// wprod: WW1 = rnd(W_r @ W1_r); bb1 = b @ W1_r + b1
// ---------------------------------------------------------------------------
__global__ void wprod_kernel(const float* __restrict__ b, const float* __restrict__ b1) {
    int idx = blockIdx.x * 256 + threadIdx.x;
    int i = idx >> 7, j = idx & 127;
    const float* W1r = g_w + 2 * DD * DD;
    float s = 0.f;
#pragma unroll 8
    for (int k = 0; k < 128; k++)
        s = fmaf(g_w[i * 128 + k], W1r[k * 128 + j], s);
    g_ww1[idx] = rnd_tf32(s);
    if (idx < 128) {
        float t = 0.f;
        for (int k = 0; k < 128; k++)
            t = fmaf(b[k], W1r[k * 128 + idx], t);
        g_bb1[idx] = t + b1[idx];
    }
}

// ---------------------------------------------------------------------------
// CSR build: histogram -> two-level scan -> scatter (4 edges per thread)
// ---------------------------------------------------------------------------
__global__ void hist_kernel(const int* __restrict__ erow, int E) {
    int i0 = (blockIdx.x * blockDim.x + threadIdx.x) * 4;
    if (i0 + 3 < E) {
        int4 r = *(const int4*)(erow + i0);
        atomicAdd(&g_cnt[r.x + 1], 1);
        atomicAdd(&g_cnt[r.y + 1], 1);
        atomicAdd(&g_cnt[r.z + 1], 1);
        atomicAdd(&g_cnt[r.w + 1], 1);
    } else {
        for (int j = 0; j < 4 && i0 + j < E; j++)
            atomicAdd(&g_cnt[erow[i0 + j] + 1], 1);
    }
}

__global__ __launch_bounds__(1024)
void scanA_kernel(int n) {
    __shared__ int sm[1024];
    int t = threadIdx.x;
    int i = blockIdx.x * 1024 + t;
    int v = (i <= n) ? g_cnt[i] : 0;
    sm[t] = v;
    __syncthreads();
#pragma unroll
    for (int off = 1; off < 1024; off <<= 1) {
        int u = (t >= off) ? sm[t - off] : 0;
        __syncthreads();
        sm[t] += u;
        __syncthreads();
    }
    if (i <= n) g_cnt[i] = sm[t];
    if (t == 1023) g_blksum[blockIdx.x] = sm[1023];
}

__global__ void scanB_kernel(int nb) {
    __shared__ int sm[64];
    int t = threadIdx.x;
    int v = (t < nb) ? g_blksum[t] : 0;
    sm[t] = v;
    __syncthreads();
#pragma unroll
    for (int off = 1; off < 64; off <<= 1) {
        int u = (t >= off) ? sm[t - off] : 0;
        __syncthreads();
        sm[t] += u;
        __syncthreads();
    }
    if (t < nb) g_blkoff[t] = sm[t] - v;
}

__global__ __launch_bounds__(1024)
void scanC_kernel(int n) {
    int i = blockIdx.x * 1024 + threadIdx.x;
    if (i <= n) {
        int v = g_cnt[i] + g_blkoff[blockIdx.x];
        g_cnt[i] = v;
        if (i < n) g_cursor[i] = v;
    }
}

__global__ void scatter_kernel(const int* __restrict__ erow, const int* __restrict__ ecol,
                               const float* __restrict__ eval, int E) {
    int i0 = (blockIdx.x * blockDim.x + threadIdx.x) * 4;
    if (i0 + 3 < E) {
        int4 r = *(const int4*)(erow + i0);
        int4 c = *(const int4*)(ecol + i0);
        float4 v = *(const float4*)(eval + i0);
        int p0 = atomicAdd(&g_cursor[r.x], 1);
        int p1 = atomicAdd(&g_cursor[r.y], 1);
        int p2 = atomicAdd(&g_cursor[r.z], 1);
        int p3 = atomicAdd(&g_cursor[r.w], 1);
        g_epk[p0] = make_int2(c.x, __float_as_int(v.x));
        g_epk[p1] = make_int2(c.y, __float_as_int(v.y));
        g_epk[p2] = make_int2(c.z, __float_as_int(v.z));
        g_epk[p3] = make_int2(c.w, __float_as_int(v.w));
    } else {
        for (int j = 0; j < 4 && i0 + j < E; j++) {
            int pos = atomicAdd(&g_cursor[erow[i0 + j]], 1);
            g_epk[pos] = make_int2(ecol[i0 + j], __float_as_int(eval[i0 + j]));
        }
    }
}

// ---------------------------------------------------------------------------
// CSR SpMM: one warp per row, uniform edge reads, 2-edge unroll.
// ---------------------------------------------------------------------------
__global__ __launch_bounds__(256)
void spmm_csr(const float* __restrict__ x, const float* __restrict__ perb,
              float* __restrict__ ax, float* __restrict__ as, int n) {
    int r = (int)((blockIdx.x * (size_t)blockDim.x + threadIdx.x) >> 5);
    if (r >= n) return;
    int lane = threadIdx.x & 31;
    int e = g_cnt[r], end = g_cnt[r + 1];
    const int off = lane * 4;
    float4 a0 = make_float4(0.f, 0.f, 0.f, 0.f);
    float4 s0 = make_float4(0.f, 0.f, 0.f, 0.f);
    float4 a1 = make_float4(0.f, 0.f, 0.f, 0.f);
    float4 s1 = make_float4(0.f, 0.f, 0.f, 0.f);
    for (; e + 2 <= end; e += 2) {
        int2 p0 = g_epk[e];
        int2 p1 = g_epk[e + 1];
        float v0 = __int_as_float(p0.y);
        float v1 = __int_as_float(p1.y);
        size_t c0 = (size_t)p0.x * 128 + off;
        size_t c1 = (size_t)p1.x * 128 + off;
        float4 xv0 = *(const float4*)(x + c0);
        float4 pv0 = *(const float4*)(perb + c0);
        float4 xv1 = *(const float4*)(x + c1);
        float4 pv1 = *(const float4*)(perb + c1);
        a0.x = fmaf(v0, xv0.x, a0.x); a0.y = fmaf(v0, xv0.y, a0.y);
        a0.z = fmaf(v0, xv0.z, a0.z); a0.w = fmaf(v0, xv0.w, a0.w);
        s0.x = fmaf(v0, xv0.x + pv0.x, s0.x); s0.y = fmaf(v0, xv0.y + pv0.y, s0.y);
        s0.z = fmaf(v0, xv0.z + pv0.z, s0.z); s0.w = fmaf(v0, xv0.w + pv0.w, s0.w);
        a1.x = fmaf(v1, xv1.x, a1.x); a1.y = fmaf(v1, xv1.y, a1.y);
        a1.z = fmaf(v1, xv1.z, a1.z); a1.w = fmaf(v1, xv1.w, a1.w);
        s1.x = fmaf(v1, xv1.x + pv1.x, s1.x); s1.y = fmaf(v1, xv1.y + pv1.y, s1.y);
        s1.z = fmaf(v1, xv1.z + pv1.z, s1.z); s1.w = fmaf(v1, xv1.w + pv1.w, s1.w);
    }
    if (e < end) {
        int2 p0 = g_epk[e];
        float v0 = __int_as_float(p0.y);
        size_t c0 = (size_t)p0.x * 128 + off;
        float4 xv0 = *(const float4*)(x + c0);
        float4 pv0 = *(const float4*)(perb + c0);
        a0.x = fmaf(v0, xv0.x, a0.x); a0.y = fmaf(v0, xv0.y, a0.y);
        a0.z = fmaf(v0, xv0.z, a0.z); a0.w = fmaf(v0, xv0.w, a0.w);
        s0.x = fmaf(v0, xv0.x + pv0.x, s0.x); s0.y = fmaf(v0, xv0.y + pv0.y, s0.y);
        s0.z = fmaf(v0, xv0.z + pv0.z, s0.z); s0.w = fmaf(v0, xv0.w + pv0.w, s0.w);
    }
    a0.x += a1.x; a0.y += a1.y; a0.z += a1.z; a0.w += a1.w;
    s0.x += s1.x; s0.y += s1.y; s0.z += s1.z; s0.w += s1.w;
    size_t ro = (size_t)r * 128 + off;
    *(float4*)(ax + ro) = a0;
    *(float4*)(as + ro) = s0;
}

// ---------------------------------------------------------------------------
// PHASE0 multi-output GEMM: A tile staged ONCE in smem, 2-3 B passes reuse it.
// set 0 (A=AX): pass0 TY=@Wt+bt ; pass1 U1=@WW1+bb1 (stats0)
// set 1 (A=AS): pass0 TX=@Wt+bt ; pass1 emb=@W+b+x+perb ; pass2 U2=@WW1+bb1 (stats1)
// 512 thr / 16 warps (8M x 2N), warp tile 16x64, B double-buffered cp.async.
// ---------------------------------------------------------------------------
#define APF 132                      // full A tile pitch (132 % 32 == 4, conflict-free)
#define ACHF (128 * APF)             // full A tile words
#define BP_ 136
#define BCH (32 * BP_)
#define RED0_OFF (ACHF + 2 * BCH)
#define SMEM0_BYTES ((RED0_OFF + 384) * 4)

__global__ __launch_bounds__(512, 2)
void fgemm0(const float* __restrict__ AX, const float* __restrict__ AS,
            float* __restrict__ TY, float* __restrict__ TX,
            float* __restrict__ U1, float* __restrict__ U2,
            const float* __restrict__ b, const float* __restrict__ bt,
            const float* __restrict__ xsrc, const float* __restrict__ psrc,
            float* __restrict__ emb, int n) {
    extern __shared__ float smf[];
    uint32_t sb = smem_u32(smf);
    float* redf = smf + RED0_OFF;

    const int tid = threadIdx.x;
    const int wid = tid >> 5;
    const int lane = tid & 31;
    const int grp = lane >> 2;
    const int tig = lane & 3;
    const int wm = wid >> 1;
    const int wn = wid & 1;
    const int set = blockIdx.x;
    const int m0 = blockIdx.y * 128;

    const float* A = set ? AS : AX;
    const int npass = set ? 3 : 2;

    // ---- stage full A tile (64KB) via cp.async, own group ----
#pragma unroll
    for (int it = 0; it < 8; it++) {
        int idx = tid + it * 512;        // 0..4095 float4 slots
        int row = idx >> 5, c4 = idx & 31;
        uint32_t dst = sb + (uint32_t)((row * APF + c4 * 4) * 4);
        cp16(dst, A + (size_t)(m0 + row) * 128 + c4 * 4, (m0 + row) < n);
    }
    CP_COMMIT();

    auto issueB = [&](const float* Bm, int c, int s) {
        const int kb = c * 32;
#pragma unroll
        for (int j = 0; j < 2; j++) {
            int f = tid + j * 512;
            int kr = f >> 5, c4 = f & 31;
            uint32_t dst = sb + (uint32_t)((ACHF + s * BCH + kr * BP_ + c4 * 4) * 4);
            cp16(dst, Bm + (size_t)(kb + kr) * 128 + c4 * 4, true);
        }
        CP_COMMIT();
    };

    const int r0 = m0 + wm * 16 + grp;
    const int r1 = r0 + 8;
    const bool ok0 = r0 < n, ok1 = r1 < n;

    for (int pass = 0; pass < npass; pass++) {
        const float* Bm;
        const float* bias;
        float* outp = nullptr;
        bool do_emb = false, do_stats = false;
        int statset = 0;
        if (set == 0) {
            if (pass == 0) { Bm = g_w + DD * DD; bias = bt;    outp = TY; }
            else           { Bm = g_ww1;         bias = g_bb1; outp = U1; do_stats = true; statset = 0; }
        } else {
            if (pass == 0)      { Bm = g_w + DD * DD; bias = bt;    outp = TX; }
            else if (pass == 1) { Bm = g_w;           bias = b;     outp = emb; do_emb = true; }
            else                { Bm = g_ww1;         bias = g_bb1; outp = U2; do_stats = true; statset = 1; }
        }

        if (do_stats && tid < 256) redf[tid] = 0.f;

        float acc[8][4];
#pragma unroll
        for (int j = 0; j < 8; j++)
#pragma unroll
            for (int q = 0; q < 4; q++) acc[j][q] = 0.f;

        issueB(Bm, 0, 0);
        for (int c = 0; c < 4; c++) {
            if (c < 3) {
                issueB(Bm, c + 1, (c + 1) & 1);
                asm volatile("cp.async.wait_group 1;" ::: "memory");
            } else {
                asm volatile("cp.async.wait_group 0;" ::: "memory");
            }
            __syncthreads();
            const uint32_t* Ab = (const uint32_t*)smf;
            const uint32_t* Bb = (const uint32_t*)(smf + ACHF + (c & 1) * BCH);
#pragma unroll
            for (int ks = 0; ks < 4; ks++) {
                const int k0 = c * 32 + ks * 8;
                const uint32_t* a0p = Ab + (wm * 16 + grp) * APF + k0 + tig;
                const uint32_t* a1p = a0p + 8 * APF;
                uint32_t af0 = rndu(a0p[0]), af1 = rndu(a1p[0]);
                uint32_t af2 = rndu(a0p[4]), af3 = rndu(a1p[4]);
#pragma unroll
                for (int ni = 0; ni < 8; ni++) {
                    const uint32_t* bp = Bb + (ks * 8 + tig) * BP_ + wn * 64 + ni * 8 + grp;
                    uint32_t b0 = bp[0], b1v = bp[4 * BP_];
                    mma_tf32(acc[ni][0], acc[ni][1], acc[ni][2], acc[ni][3],
                             af0, af1, af2, af3, b0, b1v);
                }
            }
            __syncthreads();
        }

        // ---- epilogue for this pass ----
#pragma unroll
        for (int ni = 0; ni < 8; ni++) {
            int col = wn * 64 + ni * 8 + tig * 2;
            float2 bv = *(const float2*)(bias + col);
            float c0 = acc[ni][0] + bv.x, c1 = acc[ni][1] + bv.y;
            float c2 = acc[ni][2] + bv.x, c3 = acc[ni][3] + bv.y;
            if (ok0) {
                size_t o0 = (size_t)r0 * 128 + col;
                if (do_emb) {
                    float2 xv = *(const float2*)(xsrc + o0);
                    float2 pv = *(const float2*)(psrc + o0);
                    *(float2*)(outp + o0) = make_float2(c0 + xv.x + pv.x, c1 + xv.y + pv.y);
                } else {
                    *(float2*)(outp + o0) = make_float2(c0, c1);
                }
            }
            if (ok1) {
                size_t o1 = (size_t)r1 * 128 + col;
                if (do_emb) {
                    float2 xv = *(const float2*)(xsrc + o1);
                    float2 pv = *(const float2*)(psrc + o1);
                    *(float2*)(outp + o1) = make_float2(c2 + xv.x + pv.x, c3 + xv.y + pv.y);
                } else {
                    *(float2*)(outp + o1) = make_float2(c2, c3);
                }
            }
            if (do_stats) {
                float s0 = (ok0 ? c0 : 0.f) + (ok1 ? c2 : 0.f);
                float s1 = (ok0 ? c1 : 0.f) + (ok1 ? c3 : 0.f);
                float q0 = (ok0 ? c0 * c0 : 0.f) + (ok1 ? c2 * c2 : 0.f);
                float q1 = (ok0 ? c1 * c1 : 0.f) + (ok1 ? c3 * c3 : 0.f);
#pragma unroll
                for (int msk = 4; msk <= 16; msk <<= 1) {
                    s0 += __shfl_xor_sync(0xffffffffu, s0, msk);
                    s1 += __shfl_xor_sync(0xffffffffu, s1, msk);
                    q0 += __shfl_xor_sync(0xffffffffu, q0, msk);
                    q1 += __shfl_xor_sync(0xffffffffu, q1, msk);
                }
                if (grp == 0) {
                    atomicAdd(&redf[col], s0);
                    atomicAdd(&redf[col + 1], s1);
                    atomicAdd(&redf[128 + col], q0);
                    atomicAdd(&redf[128 + col + 1], q1);
                }
            }
        }

        if (do_stats) {
            __syncthreads();
            if (tid < 256)
                atomicAdd(&g_stats[statset * 256 + tid], redf[tid]);
        }
    }
}

// ---------------------------------------------------------------------------
// PHASE2: p = PReLU(BN(U))@W2+b2 (no store), fused BYOL loss vs T. (R10 form)
// ---------------------------------------------------------------------------
#define AP_ 36
#define ACH (128 * AP_)
#define RED_OFF (2 * ACH + 2 * BCH)
#define SMEM2_BYTES ((RED_OFF + 384 + 256) * 4)

__global__ __launch_bounds__(512, 2)
void fgemm2(const float* __restrict__ U1, const float* __restrict__ U2,
            const float* __restrict__ TY, const float* __restrict__ TX,
            const float* __restrict__ b2,
            const float* __restrict__ beta, const float* __restrict__ alphap,
            int n) {
    extern __shared__ float smf[];
    uint32_t sb = smem_u32(smf);
    float* redf = smf + RED_OFF;
    float* sG   = smf + RED_OFF + 384;
    float* sBp  = sG + 128;

    const int tid = threadIdx.x;
    const int wid = tid >> 5;
    const int lane = tid & 31;
    const int grp = lane >> 2;
    const int tig = lane & 3;
    const int wm = wid >> 1;
    const int wn = wid & 1;
    const int set = blockIdx.x;
    const int m0 = blockIdx.y * 128;

    const float* A = set ? U2 : U1;
    const float* Bm = g_w + 3 * DD * DD;
    const float* Tm = set ? TY : TX;

    if (tid < 384) redf[tid] = 0.f;
    float alpha = __ldg(alphap);
    if (tid < 128) {
        float mu = g_bnp[set * 256 + tid];
        float g  = g_bnp[set * 256 + 128 + tid];
        sG[tid] = g;
        sBp[tid] = beta[tid] - mu * g;
    }

    float acc[8][4];
#pragma unroll
    for (int j = 0; j < 8; j++)
#pragma unroll
        for (int q = 0; q < 4; q++) acc[j][q] = 0.f;

    auto issue = [&](int c, int s) {
        const int kb = c * 32;
#pragma unroll
        for (int j = 0; j < 2; j++) {
            int f = tid + j * 512;
            int row = f >> 3, c4 = f & 7;
            uint32_t dst = sb + (uint32_t)((s * ACH + row * AP_ + c4 * 4) * 4);
            cp16(dst, A + (size_t)(m0 + row) * 128 + kb + c4 * 4, (m0 + row) < n);
        }
#pragma unroll
        for (int j = 0; j < 2; j++) {
            int f = tid + j * 512;
            int kr = f >> 5, c4 = f & 31;
            uint32_t dst = sb + (uint32_t)((2 * ACH + s * BCH + kr * BP_ + c4 * 4) * 4);
            cp16(dst, Bm + (size_t)(kb + kr) * 128 + c4 * 4, true);
        }
        CP_COMMIT();
    };

    issue(0, 0);
    for (int c = 0; c < 4; c++) {
        if (c < 3) {
            issue(c + 1, (c + 1) & 1);
            asm volatile("cp.async.wait_group 1;" ::: "memory");
        } else {
            asm volatile("cp.async.wait_group 0;" ::: "memory");
        }
        __syncthreads();
        const uint32_t* Ab = (const uint32_t*)(smf + (c & 1) * ACH);
        const uint32_t* Bb = (const uint32_t*)(smf + 2 * ACH + (c & 1) * BCH);
#pragma unroll
        for (int ks = 0; ks < 4; ks++) {
            const int k0 = ks * 8;
            const uint32_t* a0p = Ab + (wm * 16 + grp) * AP_ + k0 + tig;
            const uint32_t* a1p = a0p + 8 * AP_;
            uint32_t af0 = a0p[0], af1 = a1p[0], af2 = a0p[4], af3 = a1p[4];
            int kA = c * 32 + k0 + tig;
            float gA = sG[kA], bA = sBp[kA];
            float gB = sG[kA + 4], bB = sBp[kA + 4];
            af0 = bnfrag(af0, gA, bA, alpha);
            af1 = bnfrag(af1, gA, bA, alpha);
            af2 = bnfrag(af2, gB, bB, alpha);
            af3 = bnfrag(af3, gB, bB, alpha);
#pragma unroll
            for (int ni = 0; ni < 8; ni++) {
                const uint32_t* bp = Bb + (k0 + tig) * BP_ + wn * 64 + ni * 8 + grp;
                uint32_t b0 = bp[0], b1v = bp[4 * BP_];
                mma_tf32(acc[ni][0], acc[ni][1], acc[ni][2], acc[ni][3],
                         af0, af1, af2, af3, b0, b1v);
            }
        }
        __syncthreads();
    }

    const int r0 = m0 + wm * 16 + grp;
    const int r1 = r0 + 8;
    const bool ok0 = r0 < n, ok1 = r1 < n;

    float pp0 = 0.f, tt0 = 0.f, pt0 = 0.f;
    float pp1 = 0.f, tt1 = 0.f, pt1 = 0.f;
#pragma unroll
    for (int ni = 0; ni < 8; ni++) {
        int col = wn * 64 + ni * 8 + tig * 2;
        float2 bv = *(const float2*)(b2 + col);
        float c0 = acc[ni][0] + bv.x, c1 = acc[ni][1] + bv.y;
        float c2 = acc[ni][2] + bv.x, c3 = acc[ni][3] + bv.y;
        if (ok0) {
            float2 t = *(const float2*)(Tm + (size_t)r0 * 128 + col);
            pp0 += c0 * c0 + c1 * c1;
            tt0 += t.x * t.x + t.y * t.y;
            pt0 += c0 * t.x + c1 * t.y;
        }
        if (ok1) {
            float2 t = *(const float2*)(Tm + (size_t)r1 * 128 + col);
            pp1 += c2 * c2 + c3 * c3;
            tt1 += t.x * t.x + t.y * t.y;
            pt1 += c2 * t.x + c3 * t.y;
        }
    }
#pragma unroll
    for (int msk = 1; msk <= 2; msk <<= 1) {
        pp0 += __shfl_xor_sync(0xffffffffu, pp0, msk);
        tt0 += __shfl_xor_sync(0xffffffffu, tt0, msk);
        pt0 += __shfl_xor_sync(0xffffffffu, pt0, msk);
        pp1 += __shfl_xor_sync(0xffffffffu, pp1, msk);
        tt1 += __shfl_xor_sync(0xffffffffu, tt1, msk);
        pt1 += __shfl_xor_sync(0xffffffffu, pt1, msk);
    }
    if (tig == 0) {
        int lr0 = wm * 16 + grp, lr1 = lr0 + 8;
        atomicAdd(&redf[lr0], pp0);
        atomicAdd(&redf[128 + lr0], tt0);
        atomicAdd(&redf[256 + lr0], pt0);
        atomicAdd(&redf[lr1], pp1);
        atomicAdd(&redf[128 + lr1], tt1);
        atomicAdd(&redf[256 + lr1], pt1);
    }
    __syncthreads();
    if (tid < 128) {
        float l = 0.f;
        if (m0 + tid < n)
            l = 2.f - 2.f * redf[256 + tid] * rsqrtf(redf[tid]) * rsqrtf(redf[128 + tid]);
#pragma unroll
        for (int o = 16; o; o >>= 1) l += __shfl_xor_sync(0xffffffffu, l, o);
        if (lane == 0) redf[320 + wid] = l;
    }
    __syncthreads();
    if (tid == 0)
        atomicAdd(&g_loss, redf[320] + redf[321] + redf[322] + redf[323]);
}

// ---------------------------------------------------------------------------
__global__ void bn_finalize(const float* __restrict__ gamma, int n) {
    int t = threadIdx.x;
    int set = t >> 7, c = t & 127;
    float s = g_stats[set * 256 + c];
    float q = g_stats[set * 256 + 128 + c];
    float mu = s / (float)n;
    float var = q / (float)n - mu * mu;
    float g = gamma[c] * rsqrtf(var + 1e-5f);
    g_bnp[set * 256 + c] = mu;
    g_bnp[set * 256 + 128 + c] = g;
}

__global__ void finish_kernel(float* __restrict__ out, int n, size_t idx) {
    out[idx] = g_loss / (float)n;
}

// ---------------------------------------------------------------------------
extern "C" void kernel_launch(void* const* d_in, const int* in_sizes, int n_in,
                              void* d_out, int out_size) {
    const float* x     = (const float*)d_in[0];
    const float* perb  = (const float*)d_in[1];
    const int*   erow  = (const int*)d_in[2];
    const int*   ecol  = (const int*)d_in[3];
    const float* eval  = (const float*)d_in[4];
    const float* W     = (const float*)d_in[5];
    const float* b     = (const float*)d_in[6];
    const float* Wt    = (const float*)d_in[7];
    const float* bt    = (const float*)d_in[8];
    const float* W1    = (const float*)d_in[9];
    const float* b1    = (const float*)d_in[10];
    const float* gamma = (const float*)d_in[11];
    const float* beta  = (const float*)d_in[12];
    const float* alpha = (const float*)d_in[13];
    const float* W2    = (const float*)d_in[14];
    const float* b2    = (const float*)d_in[15];

    const int n = in_sizes[0] / DD;
    const int E = in_sizes[2];
    float* out = (float*)d_out;

    float* buf = nullptr;
    cudaGetSymbolAddress((void**)&buf, g_buf);

    float* AX  = buf + 0 * NB;   // adj@x
    float* AS  = buf + 1 * NB;   // adj@(x+perb)
    float* TY  = buf + 2 * NB;   // target_y
    float* TX  = buf + 3 * NB;   // target_x
    float* U1  = buf + 4 * NB;
    float* U2  = buf + 5 * NB;

    cudaFuncSetAttribute(fgemm0, cudaFuncAttributeMaxDynamicSharedMemorySize, SMEM0_BYTES);
    cudaFuncSetAttribute(fgemm2, cudaFuncAttributeMaxDynamicSharedMemorySize, SMEM2_BYTES);

    // init + composed weights + CSR build
    init_kernel<<<(n + 1 + 255) / 256, 256>>>(W, Wt, W1, W2, n);
    wprod_kernel<<<64, 256>>>(b, b1);
    hist_kernel<<<(E / 4 + 255) / 256, 256>>>(erow, E);
    const int nblk = (n + 1 + 1023) / 1024;
    scanA_kernel<<<nblk, 1024>>>(n);
    scanB_kernel<<<1, 64>>>(nblk);
    scanC_kernel<<<nblk, 1024>>>(n);
    scatter_kernel<<<(E / 4 + 255) / 256, 256>>>(erow, ecol, eval, E);

    // gather-only SpMM (no atomics)
    spmm_csr<<<(int)(((long long)n * 32 + 255) / 256), 256>>>(x, perb, AX, AS, n);

    const int gbx = (n + 127) / 128;
    // PHASE0: A-resident multi-output (TY,U1 | TX,emb,U2)
    fgemm0<<<dim3(2, gbx), 512, SMEM0_BYTES>>>(AX, AS, TY, TX, U1, U2,
                                               b, bt, x, perb, out, n);
    bn_finalize<<<1, 256>>>(gamma, n);
    // PHASE2: predictor L2 + fused BYOL loss
    fgemm2<<<dim3(2, gbx), 512, SMEM2_BYTES>>>(U1, U2, TY, TX, b2, beta, alpha, n);

    finish_kernel<<<1, 1>>>(out, n, (size_t)n * DD);
}

// round 16
// speedup vs baseline: 1.0954x; 1.0954x over previous
#include <cuda_runtime.h>
#include <stdint.h>

#define DD 128
#define NMAX 50000
#define EMAX 800000
#define NB ((size_t)NMAX * DD)

// scratch (static device memory — no allocs)
__device__ __align__(16) float g_buf[6 * NB];
__device__ __align__(16) uint16_t g_pp[NB];        // bf16(perb), natural order
__device__ __align__(16) float g_w[4 * DD * DD];   // tf32-rounded W, Wt, W1, W2
__device__ __align__(16) float g_ww1[DD * DD];     // rnd(W_r @ W1_r)
__device__ float g_bb1[DD];                        // b @ W1_r + b1
__device__ float g_stats[512];   // [set][{sum,sumsq}][128]
__device__ float g_bnp[512];     // [set][{mu, gamma*rstd}][128]
__device__ float g_loss;
// CSR build
__device__ int   g_cnt[NMAX + 1];
__device__ int   g_cursor[NMAX];
__device__ int   g_blksum[64];
__device__ int   g_blkoff[64];
__device__ __align__(8) int2 g_epk[EMAX];          // packed {col, val-bits}

__device__ __forceinline__ float rnd_tf32(float f) {
    uint32_t u;
    asm("cvt.rna.tf32.f32 %0, %1;" : "=r"(u) : "f"(f));
    return __uint_as_float(u);
}

__device__ __forceinline__ uint32_t rndu(uint32_t u) {
    uint32_t o;
    asm("cvt.rna.tf32.f32 %0, %1;" : "=r"(o) : "f"(__uint_as_float(u)));
    return o;
}

__device__ __forceinline__ uint32_t pack_bf16x2(float lo, float hi) {
    uint32_t r;
    asm("cvt.rn.bf16x2.f32 %0, %1, %2;" : "=r"(r) : "f"(hi), "f"(lo));
    return r;
}

__device__ __forceinline__ uint32_t bnfrag(uint32_t u, float g, float bp, float alpha) {
    float v = __uint_as_float(u);
    v = fmaf(v, g, bp);
    v = fmaxf(v, 0.f) + alpha * fminf(v, 0.f);
    uint32_t o;
    asm("cvt.rna.tf32.f32 %0, %1;" : "=r"(o) : "f"(v));
    return o;
}

__device__ __forceinline__ void mma_tf32(float& d0, float& d1, float& d2, float& d3,
                                         uint32_t a0, uint32_t a1, uint32_t a2, uint32_t a3,
                                         uint32_t b0, uint32_t b1) {
    asm volatile(
        "mma.sync.aligned.m16n8k8.row.col.f32.tf32.tf32.f32 "
        "{%0,%1,%2,%3}, {%4,%5,%6,%7}, {%8,%9}, {%0,%1,%2,%3};"
        : "+f"(d0), "+f"(d1), "+f"(d2), "+f"(d3)
        : "r"(a0), "r"(a1), "r"(a2), "r"(a3), "r"(b0), "r"(b1));
}

__device__ __forceinline__ uint32_t smem_u32(const void* p) {
    uint32_t a;
    asm("{ .reg .u64 t; cvta.to.shared.u64 t, %1; cvt.u32.u64 %0, t; }" : "=r"(a) : "l"(p));
    return a;
}

__device__ __forceinline__ void cp16(uint32_t dst, const void* src, bool pred) {
    int sz = pred ? 16 : 0;
    asm volatile("cp.async.cg.shared.global [%0], [%1], 16, %2;"
                 :: "r"(dst), "l"(src), "r"(sz) : "memory");
}
#define CP_COMMIT() asm volatile("cp.async.commit_group;" ::: "memory")

// ---------------------------------------------------------------------------
// init: zero hist/stats/loss; round weight matrices into g_w
// ---------------------------------------------------------------------------
__global__ void init_kernel(const float* __restrict__ W, const float* __restrict__ Wt,
                            const float* __restrict__ W1, const float* __restrict__ W2,
                            int n) {
    int i = blockIdx.x * blockDim.x + threadIdx.x;
    if (i < 512) g_stats[i] = 0.f;
    if (i == 0) g_loss = 0.f;
    if (i <= n) g_cnt[i] = 0;
    if (i < DD * DD) {
        g_w[i]               = rnd_tf32(W[i]);
        g_w[DD * DD + i]     = rnd_tf32(Wt[i]);
        g_w[2 * DD * DD + i] = rnd_tf32(W1[i]);
        g_w[3 * DD * DD + i] = rnd_tf32(W2[i]);
    }
}

// ---------------------------------------------------------------------------
// pack_pp: g_pp[i] = bf16(perb[i]), 4 elems per thread
// ---------------------------------------------------------------------------
__global__ void pack_pp(const float* __restrict__ perb, int total4) {
    int i = blockIdx.x * blockDim.x + threadIdx.x;
    if (i >= total4) return;
    float4 pv = ((const float4*)perb)[i];
    uint2 o;
    o.x = pack_bf16x2(pv.x, pv.y);
    o.y = pack_bf16x2(pv.z, pv.w);
    ((uint2*)g_pp)[i] = o;
}

// ---------------------------------------------------------------------------
// wprod: WW1 = rnd(W_r @ W1_r); bb1 = b @ W1_r + b1
// ---------------------------------------------------------------------------
__global__ void wprod_kernel(const float* __restrict__ b, const float* __restrict__ b1) {
    int idx = blockIdx.x * 256 + threadIdx.x;
    int i = idx >> 7, j = idx & 127;
    const float* W1r = g_w + 2 * DD * DD;
    float s = 0.f;
#pragma unroll 8
    for (int k = 0; k < 128; k++)
        s = fmaf(g_w[i * 128 + k], W1r[k * 128 + j], s);
    g_ww1[idx] = rnd_tf32(s);
    if (idx < 128) {
        float t = 0.f;
        for (int k = 0; k < 128; k++)
            t = fmaf(b[k], W1r[k * 128 + idx], t);
        g_bb1[idx] = t + b1[idx];
    }
}

// ---------------------------------------------------------------------------
// CSR build: histogram -> two-level scan -> scatter (4 edges per thread)
// ---------------------------------------------------------------------------
__global__ void hist_kernel(const int* __restrict__ erow, int E) {
    int i0 = (blockIdx.x * blockDim.x + threadIdx.x) * 4;
    if (i0 + 3 < E) {
        int4 r = *(const int4*)(erow + i0);
        atomicAdd(&g_cnt[r.x + 1], 1);
        atomicAdd(&g_cnt[r.y + 1], 1);
        atomicAdd(&g_cnt[r.z + 1], 1);
        atomicAdd(&g_cnt[r.w + 1], 1);
    } else {
        for (int j = 0; j < 4 && i0 + j < E; j++)
            atomicAdd(&g_cnt[erow[i0 + j] + 1], 1);
    }
}

__global__ __launch_bounds__(1024)
void scanA_kernel(int n) {
    __shared__ int sm[1024];
    int t = threadIdx.x;
    int i = blockIdx.x * 1024 + t;
    int v = (i <= n) ? g_cnt[i] : 0;
    sm[t] = v;
    __syncthreads();
#pragma unroll
    for (int off = 1; off < 1024; off <<= 1) {
        int u = (t >= off) ? sm[t - off] : 0;
        __syncthreads();
        sm[t] += u;
        __syncthreads();
    }
    if (i <= n) g_cnt[i] = sm[t];
    if (t == 1023) g_blksum[blockIdx.x] = sm[1023];
}

__global__ void scanB_kernel(int nb) {
    __shared__ int sm[64];
    int t = threadIdx.x;
    int v = (t < nb) ? g_blksum[t] : 0;
    sm[t] = v;
    __syncthreads();
#pragma unroll
    for (int off = 1; off < 64; off <<= 1) {
        int u = (t >= off) ? sm[t - off] : 0;
        __syncthreads();
        sm[t] += u;
        __syncthreads();
    }
    if (t < nb) g_blkoff[t] = sm[t] - v;
}

__global__ __launch_bounds__(1024)
void scanC_kernel(int n) {
    int i = blockIdx.x * 1024 + threadIdx.x;
    if (i <= n) {
        int v = g_cnt[i] + g_blkoff[blockIdx.x];
        g_cnt[i] = v;
        if (i < n) g_cursor[i] = v;
    }
}

__global__ void scatter_kernel(const int* __restrict__ erow, const int* __restrict__ ecol,
                               const float* __restrict__ eval, int E) {
    int i0 = (blockIdx.x * blockDim.x + threadIdx.x) * 4;
    if (i0 + 3 < E) {
        int4 r = *(const int4*)(erow + i0);
        int4 c = *(const int4*)(ecol + i0);
        float4 v = *(const float4*)(eval + i0);
        int p0 = atomicAdd(&g_cursor[r.x], 1);
        int p1 = atomicAdd(&g_cursor[r.y], 1);
        int p2 = atomicAdd(&g_cursor[r.z], 1);
        int p3 = atomicAdd(&g_cursor[r.w], 1);
        g_epk[p0] = make_int2(c.x, __float_as_int(v.x));
        g_epk[p1] = make_int2(c.y, __float_as_int(v.y));
        g_epk[p2] = make_int2(c.z, __float_as_int(v.z));
        g_epk[p3] = make_int2(c.w, __float_as_int(v.w));
    } else {
        for (int j = 0; j < 4 && i0 + j < E; j++) {
            int pos = atomicAdd(&g_cursor[erow[i0 + j]], 1);
            g_epk[pos] = make_int2(ecol[i0 + j], __float_as_int(eval[i0 + j]));
        }
    }
}

// ---------------------------------------------------------------------------
// CSR SpMM: one warp per row; x gathered fp32 (exact), perb gathered bf16.
// AX[r] = sum v*x[c] (exact fp32);  AS[r] = sum v*(x[c] + bf16(perb[c]))
// 24B/edge-lane vs 32B -> 25% less L2 gather traffic.
// ---------------------------------------------------------------------------
__global__ __launch_bounds__(256)
void spmm_csr(const float* __restrict__ x,
              float* __restrict__ ax, float* __restrict__ as, int n) {
    int r = (int)((blockIdx.x * (size_t)blockDim.x + threadIdx.x) >> 5);
    if (r >= n) return;
    int lane = threadIdx.x & 31;
    int e = g_cnt[r], end = g_cnt[r + 1];
    const int off = lane * 4;
    float4 a0 = make_float4(0.f, 0.f, 0.f, 0.f);
    float4 s0 = make_float4(0.f, 0.f, 0.f, 0.f);
    float4 a1 = make_float4(0.f, 0.f, 0.f, 0.f);
    float4 s1 = make_float4(0.f, 0.f, 0.f, 0.f);

#define ACC_EDGE(xv, pw, v, aa, ss)                                          \
    do {                                                                     \
        float p0_ = __uint_as_float((pw).x << 16);                           \
        float p1_ = __uint_as_float((pw).x & 0xFFFF0000u);                   \
        float p2_ = __uint_as_float((pw).y << 16);                           \
        float p3_ = __uint_as_float((pw).y & 0xFFFF0000u);                   \
        (aa).x = fmaf(v, (xv).x, (aa).x); (aa).y = fmaf(v, (xv).y, (aa).y);  \
        (aa).z = fmaf(v, (xv).z, (aa).z); (aa).w = fmaf(v, (xv).w, (aa).w);  \
        (ss).x = fmaf(v, (xv).x + p0_, (ss).x);                              \
        (ss).y = fmaf(v, (xv).y + p1_, (ss).y);                              \
        (ss).z = fmaf(v, (xv).z + p2_, (ss).z);                              \
        (ss).w = fmaf(v, (xv).w + p3_, (ss).w);                              \
    } while (0)

    for (; e + 2 <= end; e += 2) {
        int2 p0 = g_epk[e];
        int2 p1 = g_epk[e + 1];
        float v0 = __int_as_float(p0.y);
        float v1 = __int_as_float(p1.y);
        size_t c0 = (size_t)p0.x * 128 + off;
        size_t c1 = (size_t)p1.x * 128 + off;
        float4 xv0 = *(const float4*)(x + c0);
        uint2  pw0 = *(const uint2*)(g_pp + c0);
        float4 xv1 = *(const float4*)(x + c1);
        uint2  pw1 = *(const uint2*)(g_pp + c1);
        ACC_EDGE(xv0, pw0, v0, a0, s0);
        ACC_EDGE(xv1, pw1, v1, a1, s1);
    }
    if (e < end) {
        int2 p0 = g_epk[e];
        float v0 = __int_as_float(p0.y);
        size_t c0 = (size_t)p0.x * 128 + off;
        float4 xv0 = *(const float4*)(x + c0);
        uint2  pw0 = *(const uint2*)(g_pp + c0);
        ACC_EDGE(xv0, pw0, v0, a0, s0);
    }
#undef ACC_EDGE
    a0.x += a1.x; a0.y += a1.y; a0.z += a1.z; a0.w += a1.w;
    s0.x += s1.x; s0.y += s1.y; s0.z += s1.z; s0.w += s1.w;
    size_t ro = (size_t)r * 128 + off;
    *(float4*)(ax + ro) = a0;
    *(float4*)(as + ro) = s0;
}

// ---------------------------------------------------------------------------
// Pipelined tf32 GEMM, cp.async ping-pong, BK=32 x 4 chunks, 512 thr / 16 warps.
// PHASE 0 (5 sets): 0: TY=AX@Wt+bt       1: U1=AX@WW1+bb1 (stats0)
//                   2: TX=AS@Wt+bt       3: emb=AS@W+b+x+perb (no EX store)
//                   4: U2=AS@WW1+bb1 (stats1)
// PHASE 2 (2 sets): p=PReLU(BN(U))@W2+b2 (no store), fused BYOL loss vs T
// ---------------------------------------------------------------------------
#define AP_ 36
#define BP_ 136
#define ACH (128 * AP_)
#define BCH (32 * BP_)
#define RED_OFF (2 * ACH + 2 * BCH)
#define SMEM_BYTES ((RED_OFF + 384 + 256) * 4)

template <int PHASE>
__global__ __launch_bounds__(512, 2)
void fgemm(const float* __restrict__ AX, const float* __restrict__ AS,
           float* __restrict__ TY, float* __restrict__ TX,
           float* __restrict__ U1, float* __restrict__ U2,
           const float* __restrict__ b, const float* __restrict__ bt,
           const float* __restrict__ b2,
           const float* __restrict__ beta, const float* __restrict__ alphap,
           const float* __restrict__ xsrc, const float* __restrict__ psrc,
           float* __restrict__ emb, int n) {
    extern __shared__ float smf[];
    uint32_t sb = smem_u32(smf);
    float* redf = smf + RED_OFF;
    float* sG   = smf + RED_OFF + 384;
    float* sBp  = sG + 128;

    const int tid = threadIdx.x;
    const int wid = tid >> 5;
    const int lane = tid & 31;
    const int grp = lane >> 2;
    const int tig = lane & 3;
    const int wm = wid >> 1;
    const int wn = wid & 1;
    const int set = blockIdx.x;
    const int m0 = blockIdx.y * 128;

    const float* A;
    const float* Bm;
    const float* bias;
    float* outp = nullptr;
    const float* Tm = nullptr;
    bool do_emb = false, do_stats = false;
    int statset = 0;
    if (PHASE == 0) {
        A = (set >= 2) ? AS : AX;
        if (set == 0)      { Bm = g_w + DD * DD; bias = bt;    outp = TY; }
        else if (set == 1) { Bm = g_ww1;         bias = g_bb1; outp = U1; do_stats = true; statset = 0; }
        else if (set == 2) { Bm = g_w + DD * DD; bias = bt;    outp = TX; }
        else if (set == 3) { Bm = g_w;           bias = b;     outp = emb; do_emb = true; }
        else               { Bm = g_ww1;         bias = g_bb1; outp = U2; do_stats = true; statset = 1; }
    } else {
        A = set ? U2 : U1;
        Bm = g_w + 3 * DD * DD;
        bias = b2;
        Tm = set ? TY : TX;
    }

    if (tid < 384) redf[tid] = 0.f;
    float alpha = 0.f;
    if (PHASE == 2) {
        alpha = __ldg(alphap);
        if (tid < 128) {
            float mu = g_bnp[set * 256 + tid];
            float g  = g_bnp[set * 256 + 128 + tid];
            sG[tid] = g;
            sBp[tid] = beta[tid] - mu * g;
        }
    }

    float acc[8][4];
#pragma unroll
    for (int j = 0; j < 8; j++)
#pragma unroll
        for (int q = 0; q < 4; q++) acc[j][q] = 0.f;

    auto issue = [&](int c, int s) {
        const int kb = c * 32;
#pragma unroll
        for (int j = 0; j < 2; j++) {
            int f = tid + j * 512;
            int row = f >> 3, c4 = f & 7;
            uint32_t dst = sb + (uint32_t)((s * ACH + row * AP_ + c4 * 4) * 4);
            cp16(dst, A + (size_t)(m0 + row) * 128 + kb + c4 * 4, (m0 + row) < n);
        }
#pragma unroll
        for (int j = 0; j < 2; j++) {
            int f = tid + j * 512;
            int kr = f >> 5, c4 = f & 31;
            uint32_t dst = sb + (uint32_t)((2 * ACH + s * BCH + kr * BP_ + c4 * 4) * 4);
            cp16(dst, Bm + (size_t)(kb + kr) * 128 + c4 * 4, true);
        }
        CP_COMMIT();
    };

    issue(0, 0);
    for (int c = 0; c < 4; c++) {
        if (c < 3) {
            issue(c + 1, (c + 1) & 1);
            asm volatile("cp.async.wait_group 1;" ::: "memory");
        } else {
            asm volatile("cp.async.wait_group 0;" ::: "memory");
        }
        __syncthreads();
        const uint32_t* Ab = (const uint32_t*)(smf + (c & 1) * ACH);
        const uint32_t* Bb = (const uint32_t*)(smf + 2 * ACH + (c & 1) * BCH);
#pragma unroll
        for (int ks = 0; ks < 4; ks++) {
            const int k0 = ks * 8;
            const uint32_t* a0p = Ab + (wm * 16 + grp) * AP_ + k0 + tig;
            const uint32_t* a1p = a0p + 8 * AP_;
            uint32_t af0 = a0p[0], af1 = a1p[0], af2 = a0p[4], af3 = a1p[4];
            if (PHASE == 2) {
                int kA = c * 32 + k0 + tig;
                float gA = sG[kA], bA = sBp[kA];
                float gB = sG[kA + 4], bB = sBp[kA + 4];
                af0 = bnfrag(af0, gA, bA, alpha);
                af1 = bnfrag(af1, gA, bA, alpha);
                af2 = bnfrag(af2, gB, bB, alpha);
                af3 = bnfrag(af3, gB, bB, alpha);
            } else {
                af0 = rndu(af0); af1 = rndu(af1);
                af2 = rndu(af2); af3 = rndu(af3);
            }
#pragma unroll
            for (int ni = 0; ni < 8; ni++) {
                const uint32_t* bp = Bb + (k0 + tig) * BP_ + wn * 64 + ni * 8 + grp;
                uint32_t b0 = bp[0], b1v = bp[4 * BP_];
                mma_tf32(acc[ni][0], acc[ni][1], acc[ni][2], acc[ni][3],
                         af0, af1, af2, af3, b0, b1v);
            }
        }
        __syncthreads();
    }

    const int r0 = m0 + wm * 16 + grp;
    const int r1 = r0 + 8;
    const bool ok0 = r0 < n, ok1 = r1 < n;

    if (PHASE == 2) {
        float pp0 = 0.f, tt0 = 0.f, pt0 = 0.f;
        float pp1 = 0.f, tt1 = 0.f, pt1 = 0.f;
#pragma unroll
        for (int ni = 0; ni < 8; ni++) {
            int col = wn * 64 + ni * 8 + tig * 2;
            float2 bv = *(const float2*)(bias + col);
            float c0 = acc[ni][0] + bv.x, c1 = acc[ni][1] + bv.y;
            float c2 = acc[ni][2] + bv.x, c3 = acc[ni][3] + bv.y;
            if (ok0) {
                float2 t = *(const float2*)(Tm + (size_t)r0 * 128 + col);
                pp0 += c0 * c0 + c1 * c1;
                tt0 += t.x * t.x + t.y * t.y;
                pt0 += c0 * t.x + c1 * t.y;
            }
            if (ok1) {
                float2 t = *(const float2*)(Tm + (size_t)r1 * 128 + col);
                pp1 += c2 * c2 + c3 * c3;
                tt1 += t.x * t.x + t.y * t.y;
                pt1 += c2 * t.x + c3 * t.y;
            }
        }
#pragma unroll
        for (int msk = 1; msk <= 2; msk <<= 1) {
            pp0 += __shfl_xor_sync(0xffffffffu, pp0, msk);
            tt0 += __shfl_xor_sync(0xffffffffu, tt0, msk);
            pt0 += __shfl_xor_sync(0xffffffffu, pt0, msk);
            pp1 += __shfl_xor_sync(0xffffffffu, pp1, msk);
            tt1 += __shfl_xor_sync(0xffffffffu, tt1, msk);
            pt1 += __shfl_xor_sync(0xffffffffu, pt1, msk);
        }
        if (tig == 0) {
            int lr0 = wm * 16 + grp, lr1 = lr0 + 8;
            atomicAdd(&redf[lr0], pp0);
            atomicAdd(&redf[128 + lr0], tt0);
            atomicAdd(&redf[256 + lr0], pt0);
            atomicAdd(&redf[lr1], pp1);
            atomicAdd(&redf[128 + lr1], tt1);
            atomicAdd(&redf[256 + lr1], pt1);
        }
        __syncthreads();
        if (tid < 128) {
            float l = 0.f;
            if (m0 + tid < n)
                l = 2.f - 2.f * redf[256 + tid] * rsqrtf(redf[tid]) * rsqrtf(redf[128 + tid]);
#pragma unroll
            for (int o = 16; o; o >>= 1) l += __shfl_xor_sync(0xffffffffu, l, o);
            if (lane == 0) redf[320 + wid] = l;
        }
        __syncthreads();
        if (tid == 0)
            atomicAdd(&g_loss, redf[320] + redf[321] + redf[322] + redf[323]);
        return;
    }

    // PHASE 0 store epilogue
#pragma unroll
    for (int ni = 0; ni < 8; ni++) {
        int col = wn * 64 + ni * 8 + tig * 2;
        float2 bv = *(const float2*)(bias + col);
        float c0 = acc[ni][0] + bv.x, c1 = acc[ni][1] + bv.y;
        float c2 = acc[ni][2] + bv.x, c3 = acc[ni][3] + bv.y;
        if (ok0) {
            size_t o0 = (size_t)r0 * 128 + col;
            if (do_emb) {
                float2 xv = *(const float2*)(xsrc + o0);
                float2 pv = *(const float2*)(psrc + o0);
                *(float2*)(outp + o0) = make_float2(c0 + xv.x + pv.x, c1 + xv.y + pv.y);
            } else {
                *(float2*)(outp + o0) = make_float2(c0, c1);
            }
        }
        if (ok1) {
            size_t o1 = (size_t)r1 * 128 + col;
            if (do_emb) {
                float2 xv = *(const float2*)(xsrc + o1);
                float2 pv = *(const float2*)(psrc + o1);
                *(float2*)(outp + o1) = make_float2(c2 + xv.x + pv.x, c3 + xv.y + pv.y);
            } else {
                *(float2*)(outp + o1) = make_float2(c2, c3);
            }
        }
        if (do_stats) {
            float s0 = (ok0 ? c0 : 0.f) + (ok1 ? c2 : 0.f);
            float s1 = (ok0 ? c1 : 0.f) + (ok1 ? c3 : 0.f);
            float q0 = (ok0 ? c0 * c0 : 0.f) + (ok1 ? c2 * c2 : 0.f);
            float q1 = (ok0 ? c1 * c1 : 0.f) + (ok1 ? c3 * c3 : 0.f);
#pragma unroll
            for (int msk = 4; msk <= 16; msk <<= 1) {
                s0 += __shfl_xor_sync(0xffffffffu, s0, msk);
                s1 += __shfl_xor_sync(0xffffffffu, s1, msk);
                q0 += __shfl_xor_sync(0xffffffffu, q0, msk);
                q1 += __shfl_xor_sync(0xffffffffu, q1, msk);
            }
            if (grp == 0) {
                atomicAdd(&redf[col], s0);
                atomicAdd(&redf[col + 1], s1);
                atomicAdd(&redf[128 + col], q0);
                atomicAdd(&redf[128 + col + 1], q1);
            }
        }
    }

    if (do_stats) {
        __syncthreads();
        if (tid < 256)
            atomicAdd(&g_stats[statset * 256 + tid], redf[tid]);
    }
}

// ---------------------------------------------------------------------------
__global__ void bn_finalize(const float* __restrict__ gamma, int n) {
    int t = threadIdx.x;
    int set = t >> 7, c = t & 127;
    float s = g_stats[set * 256 + c];
    float q = g_stats[set * 256 + 128 + c];
    float mu = s / (float)n;
    float var = q / (float)n - mu * mu;
    float g = gamma[c] * rsqrtf(var + 1e-5f);
    g_bnp[set * 256 + c] = mu;
    g_bnp[set * 256 + 128 + c] = g;
}

__global__ void finish_kernel(float* __restrict__ out, int n, size_t idx) {
    out[idx] = g_loss / (float)n;
}

// ---------------------------------------------------------------------------
extern "C" void kernel_launch(void* const* d_in, const int* in_sizes, int n_in,
                              void* d_out, int out_size) {
    const float* x     = (const float*)d_in[0];
    const float* perb  = (const float*)d_in[1];
    const int*   erow  = (const int*)d_in[2];
    const int*   ecol  = (const int*)d_in[3];
    const float* eval  = (const float*)d_in[4];
    const float* W     = (const float*)d_in[5];
    const float* b     = (const float*)d_in[6];
    const float* Wt    = (const float*)d_in[7];
    const float* bt    = (const float*)d_in[8];
    const float* W1    = (const float*)d_in[9];
    const float* b1    = (const float*)d_in[10];
    const float* gamma = (const float*)d_in[11];
    const float* beta  = (const float*)d_in[12];
    const float* alpha = (const float*)d_in[13];
    const float* W2    = (const float*)d_in[14];
    const float* b2    = (const float*)d_in[15];

    const int n = in_sizes[0] / DD;
    const int E = in_sizes[2];
    float* out = (float*)d_out;

    float* buf = nullptr;
    cudaGetSymbolAddress((void**)&buf, g_buf);

    float* AX  = buf + 0 * NB;   // adj@x (exact fp32)
    float* AS  = buf + 1 * NB;   // adj@(x + bf16(perb))
    float* TY  = buf + 2 * NB;   // target_y
    float* TX  = buf + 3 * NB;   // target_x
    float* U1  = buf + 4 * NB;
    float* U2  = buf + 5 * NB;

    cudaFuncSetAttribute(fgemm<0>, cudaFuncAttributeMaxDynamicSharedMemorySize, SMEM_BYTES);
    cudaFuncSetAttribute(fgemm<2>, cudaFuncAttributeMaxDynamicSharedMemorySize, SMEM_BYTES);

    const int total4 = n * DD / 4;

    // init + bf16 perb table + composed weights + CSR build
    init_kernel<<<(n + 1 + 255) / 256, 256>>>(W, Wt, W1, W2, n);
    pack_pp<<<(total4 + 255) / 256, 256>>>(perb, total4);
    wprod_kernel<<<64, 256>>>(b, b1);
    hist_kernel<<<(E / 4 + 255) / 256, 256>>>(erow, E);
    const int nblk = (n + 1 + 1023) / 1024;
    scanA_kernel<<<nblk, 1024>>>(n);
    scanB_kernel<<<1, 64>>>(nblk);
    scanC_kernel<<<nblk, 1024>>>(n);
    scatter_kernel<<<(E / 4 + 255) / 256, 256>>>(erow, ecol, eval, E);

    // gather-only SpMM: fp32 x + bf16 perb
    spmm_csr<<<(int)(((long long)n * 32 + 255) / 256), 256>>>(x, AX, AS, n);

    const int gbx = (n + 127) / 128;
    dim3 g5(5, gbx, 1), g2(2, gbx, 1);

    // merged encoder + predictor L1: TY, U1(stats), TX, emb, U2(stats)
    fgemm<0><<<g5, 512, SMEM_BYTES>>>(AX, AS, TY, TX, U1, U2,
                                      b, bt, b2, beta, alpha, x, perb, out, n);
    bn_finalize<<<1, 256>>>(gamma, n);
    // predictor L2 (fused BN+PReLU) + fused BYOL loss
    fgemm<2><<<g2, 512, SMEM_BYTES>>>(AX, AS, TY, TX, U1, U2,
                                      b, bt, b2, beta, alpha, x, perb, out, n);

    finish_kernel<<<1, 1>>>(out, n, (size_t)n * DD);
}